// round 14
// baseline (speedup 1.0000x reference)
#include <cuda_runtime.h>
#include <cuda_fp16.h>
#include <math.h>

#define NN 10000
#define EE 320000
#define FIN 128
#define HC 256
#define NH1 16
#define GG 64
#define LL 10
#define CAP 256
#define SPLIT 5120           // gat1/gemm2 pipeline split (multiple of 32)

typedef unsigned int u32;

// ---------------- scratch ----------------------------------------------------
__device__ __half g_h1h[NN * HC];
__device__ __half g_h2h[NN * HC];
__device__ __half g_out1h[NN * HC];  // relu(gat1_out + b1) in fp16
__device__ __half g_w1t[HC * FIN];   // W1^T fp16 [n][k]
__device__ __half g_w2t[HC * HC];    // W2^T fp16 [n][k]
__device__ float g_als1[NN * NH1];
__device__ float g_ald1[NN * NH1];
__device__ float g_als2[NN];
__device__ float g_ald2[NN];
__device__ float g_sums[GG * HC];
__device__ float g_cnts[GG];
__device__ int   g_deg[NN];
__device__ int   g_adj[NN * CAP];

__device__ __forceinline__ float leaky(float v) { return v >= 0.f ? v : 0.2f * v; }

__device__ __forceinline__ void redAdd4(float4* addr, float4 v) {
    asm volatile("red.global.add.v4.f32 [%0], {%1, %2, %3, %4};"
                 :: "l"(addr), "f"(v.x), "f"(v.y), "f"(v.z), "f"(v.w) : "memory");
}

__device__ __forceinline__ void mma16816(float* c, u32 a0, u32 a1, u32 a2, u32 a3,
                                         u32 b0, u32 b1) {
    asm volatile(
        "mma.sync.aligned.m16n8k16.row.col.f32.f16.f16.f32 "
        "{%0,%1,%2,%3}, {%4,%5,%6,%7}, {%8,%9}, {%0,%1,%2,%3};"
        : "+f"(c[0]), "+f"(c[1]), "+f"(c[2]), "+f"(c[3])
        : "r"(a0), "r"(a1), "r"(a2), "r"(a3), "r"(b0), "r"(b1));
}

__device__ __forceinline__ float red4(float v) {   // sum over 4-lane group
    v += __shfl_down_sync(0xffffffffu, v, 1);
    v += __shfl_down_sync(0xffffffffu, v, 2);
    return v;
}

// ---------------- side-stream init + adjacency --------------------------------
__global__ void init_side_k() {
    int i = blockIdx.x * blockDim.x + threadIdx.x;
    if (i < NN) g_deg[i] = 0;
    if (i < GG * HC) g_sums[i] = 0.f;
    if (i < GG) g_cnts[i] = 0.f;
}

__global__ void adj_fill(const int* __restrict__ src, const int* __restrict__ dst) {
    int i = blockIdx.x * blockDim.x + threadIdx.x;
    if (i * 4 >= EE) return;
    int4 s4 = ((const int4*)src)[i];
    int4 d4 = ((const int4*)dst)[i];
    int p;
    p = atomicAdd(&g_deg[d4.x], 1); g_adj[d4.x * CAP + p] = s4.x;
    p = atomicAdd(&g_deg[d4.y], 1); g_adj[d4.y * CAP + p] = s4.y;
    p = atomicAdd(&g_deg[d4.z], 1); g_adj[d4.z * CAP + p] = s4.z;
    p = atomicAdd(&g_deg[d4.w], 1); g_adj[d4.w * CAP + p] = s4.w;
}

// ---------------- weight transpose+convert (R11 naive, proven) ----------------
__global__ void wconv1_k(const float* __restrict__ W1) {
    int i = blockIdx.x * blockDim.x + threadIdx.x;
    if (i < FIN * HC) {
        int k = i >> 8, n = i & 255;
        g_w1t[n * FIN + k] = __float2half_rn(W1[i]);
    }
}
__global__ void wconv2_k(const float* __restrict__ W2) {
    int i = blockIdx.x * blockDim.x + threadIdx.x;
    if (i < HC * HC) {
        int k = i >> 8, n = i & 255;
        g_w2t[n * HC + k] = __float2half_rn(W2[i]);
    }
}

// ---------------- tensor-core GEMM + fused logits ------------------------------
// block: 32 rows x 256 cols, 8 warps as 2 row-groups x 4 col-groups.
#define KC 64
#define LDA 72
#define LDB 72

template <int LAYER>
__global__ void __launch_bounds__(256) gemm_mma(const float* __restrict__ Xin,
                                                const float* __restrict__ a_src,
                                                const float* __restrict__ a_dst,
                                                int row_off) {
    constexpr int K = (LAYER == 1) ? FIN : HC;
    const __half* __restrict__ Wt = (LAYER == 1) ? g_w1t : g_w2t;
    __half* __restrict__ Hout = (LAYER == 1) ? g_h1h : g_h2h;

    __shared__ __half As[32 * LDA];
    __shared__ __half Ws[256 * LDB];
    __shared__ float red_s[32][5];
    __shared__ float red_d[32][5];

    int row0 = row_off + blockIdx.x * 32;
    int tid = threadIdx.x;
    int warp = tid >> 5, lane = tid & 31;
    int gr = lane >> 2, tg = lane & 3;
    int wr = (warp & 1) * 16;
    int wc = (warp >> 1) * 64;

    float c[8][4];
#pragma unroll
    for (int t = 0; t < 8; t++)
#pragma unroll
        for (int j = 0; j < 4; j++) c[t][j] = 0.f;

    for (int kc0 = 0; kc0 < K; kc0 += KC) {
        // --- A chunk: 32 rows x 64 k ---
        {
            int r = tid >> 3, cc = (tid & 7) * 8;
            int row = row0 + r;
            uint4 pk = {0, 0, 0, 0};
            if (row < NN) {
                if (LAYER == 1) {
                    const float4* p = (const float4*)(Xin + (size_t)row * K + kc0 + cc);
                    float4 v0 = p[0], v1 = p[1];
                    __half2 h0 = __floats2half2_rn(v0.x, v0.y);
                    __half2 h1 = __floats2half2_rn(v0.z, v0.w);
                    __half2 h2 = __floats2half2_rn(v1.x, v1.y);
                    __half2 h3 = __floats2half2_rn(v1.z, v1.w);
                    pk.x = *(u32*)&h0; pk.y = *(u32*)&h1;
                    pk.z = *(u32*)&h2; pk.w = *(u32*)&h3;
                } else {
                    pk = *(const uint4*)(g_out1h + (size_t)row * K + kc0 + cc);
                }
            }
            *(uint4*)(As + r * LDA + cc) = pk;
        }
        // --- W chunk: 256 n-rows x 64 k ---
        {
            int cc = (tid & 7) * 8;
#pragma unroll
            for (int pass = 0; pass < 8; pass++) {
                int n = pass * 32 + (tid >> 3);
                uint4 v = *(const uint4*)(Wt + (size_t)n * K + kc0 + cc);
                *(uint4*)(Ws + n * LDB + cc) = v;
            }
        }
        __syncthreads();

#pragma unroll
        for (int ks = 0; ks < KC; ks += 16) {
            u32 a0 = *(u32*)&As[(wr + gr) * LDA + ks + tg * 2];
            u32 a1 = *(u32*)&As[(wr + gr + 8) * LDA + ks + tg * 2];
            u32 a2 = *(u32*)&As[(wr + gr) * LDA + ks + tg * 2 + 8];
            u32 a3 = *(u32*)&As[(wr + gr + 8) * LDA + ks + tg * 2 + 8];
#pragma unroll
            for (int t = 0; t < 8; t++) {
                int n = wc + t * 8 + gr;
                u32 b0 = *(u32*)&Ws[n * LDB + ks + tg * 2];
                u32 b1 = *(u32*)&Ws[n * LDB + ks + tg * 2 + 8];
                mma16816(c[t], a0, a1, a2, a3, b0, b1);
            }
        }
        __syncthreads();
    }

    int r_a = row0 + wr + gr;
    int r_b = r_a + 8;

    float vsa[8], vda[8], vsb[8], vdb[8];
#pragma unroll
    for (int t = 0; t < 8; t++) {
        int col = wc + t * 8 + tg * 2;
        if (r_a < NN) {
            __half2 ha = __floats2half2_rn(c[t][0], c[t][1]);
            *(u32*)&Hout[(size_t)r_a * HC + col] = *(u32*)&ha;
        }
        if (r_b < NN) {
            __half2 hb = __floats2half2_rn(c[t][2], c[t][3]);
            *(u32*)&Hout[(size_t)r_b * HC + col] = *(u32*)&hb;
        }
        float as0 = a_src[col], as1 = a_src[col + 1];
        float ad0 = a_dst[col], ad1 = a_dst[col + 1];
        vsa[t] = c[t][0] * as0 + c[t][1] * as1;
        vda[t] = c[t][0] * ad0 + c[t][1] * ad1;
        vsb[t] = c[t][2] * as0 + c[t][3] * as1;
        vdb[t] = c[t][2] * ad0 + c[t][3] * ad1;
    }

    if (LAYER == 1) {
        int hb = (warp >> 1) * 4;
#pragma unroll
        for (int h = 0; h < 4; h++) {
            float sa = red4(vsa[2 * h] + vsa[2 * h + 1]);
            float da = red4(vda[2 * h] + vda[2 * h + 1]);
            float sb = red4(vsb[2 * h] + vsb[2 * h + 1]);
            float db = red4(vdb[2 * h] + vdb[2 * h + 1]);
            if (tg == 0) {
                if (r_a < NN) { g_als1[r_a * NH1 + hb + h] = sa; g_ald1[r_a * NH1 + hb + h] = da; }
                if (r_b < NN) { g_als1[r_b * NH1 + hb + h] = sb; g_ald1[r_b * NH1 + hb + h] = db; }
            }
        }
    } else {
        float sa = red4(vsa[0] + vsa[1] + vsa[2] + vsa[3] + vsa[4] + vsa[5] + vsa[6] + vsa[7]);
        float da = red4(vda[0] + vda[1] + vda[2] + vda[3] + vda[4] + vda[5] + vda[6] + vda[7]);
        float sb = red4(vsb[0] + vsb[1] + vsb[2] + vsb[3] + vsb[4] + vsb[5] + vsb[6] + vsb[7]);
        float db = red4(vdb[0] + vdb[1] + vdb[2] + vdb[3] + vdb[4] + vdb[5] + vdb[6] + vdb[7]);
        if (tg == 0) {
            int cg = warp >> 1;
            red_s[wr + gr][cg] = sa; red_s[wr + gr + 8][cg] = sb;
            red_d[wr + gr][cg] = da; red_d[wr + gr + 8][cg] = db;
        }
        __syncthreads();
        if (tid < 64) {
            int row = tid >> 1, sel = tid & 1;
            if (row0 + row < NN) {
                const float (*rp)[5] = sel ? red_d : red_s;
                float s = rp[row][0] + rp[row][1] + rp[row][2] + rp[row][3];
                if (sel) g_ald2[row0 + row] = s;
                else     g_als2[row0 + row] = s;
            }
        }
    }
}

// ---------------- fused GAT layer 1: fp16 gather, epilogue b1+relu fp16 -------
__global__ void __launch_bounds__(256) gat1_k(const float* __restrict__ b1,
                                              int node_off, int node_end) {
    int w = node_off + ((blockIdx.x * blockDim.x + threadIdx.x) >> 5);
    int lane = threadIdx.x & 31;
    if (w >= node_end) return;
    const int d = w;
    const int hh = lane >> 1;

    float ald_h = g_ald1[d * NH1 + hh];
    float wself = __expf(leaky(g_als1[d * NH1 + hh] + ald_h));
    float ssum = wself;

    float acc[8];
    {
        uint4 q = *((const uint4*)(g_h1h + (size_t)d * HC) + lane);
        const __half2* h2 = (const __half2*)&q;
#pragma unroll
        for (int k = 0; k < 4; k++) {
            float2 f = __half22float2(h2[k]);
            acc[2 * k] = wself * f.x;
            acc[2 * k + 1] = wself * f.y;
        }
    }

    int beg = d * CAP;
    int end = beg + g_deg[d];

#define GAT1_STEP(SRC)                                                          \
    {                                                                           \
        int s_ = (SRC);                                                         \
        float we = __expf(leaky(g_als1[s_ * NH1 + hh] + ald_h));                \
        ssum += we;                                                             \
        uint4 q = *((const uint4*)(g_h1h + (size_t)s_ * HC) + lane);            \
        const __half2* h2 = (const __half2*)&q;                                 \
        _Pragma("unroll")                                                       \
        for (int k = 0; k < 4; k++) {                                           \
            float2 f = __half22float2(h2[k]);                                   \
            acc[2 * k]     = fmaf(we, f.x, acc[2 * k]);                         \
            acc[2 * k + 1] = fmaf(we, f.y, acc[2 * k + 1]);                     \
        }                                                                       \
    }

    for (int base = beg; base < end; base += 32) {
        int idx = base + lane;
        int sv = (idx < end) ? g_adj[idx] : 0;
        int n = min(32, end - base);
        if (n == 32) {
#pragma unroll 8
            for (int j = 0; j < 32; j++) GAT1_STEP(__shfl_sync(0xffffffffu, sv, j));
        } else {
            for (int j = 0; j < n; j++) GAT1_STEP(__shfl_sync(0xffffffffu, sv, j));
        }
    }

    float inv = 1.f / ssum;
    const float4* b4 = (const float4*)(b1 + lane * 8);
    float4 bb0 = b4[0], bb1 = b4[1];
    float o0 = fmaxf(acc[0] * inv + bb0.x, 0.f);
    float o1 = fmaxf(acc[1] * inv + bb0.y, 0.f);
    float o2 = fmaxf(acc[2] * inv + bb0.z, 0.f);
    float o3 = fmaxf(acc[3] * inv + bb0.w, 0.f);
    float o4 = fmaxf(acc[4] * inv + bb1.x, 0.f);
    float o5 = fmaxf(acc[5] * inv + bb1.y, 0.f);
    float o6 = fmaxf(acc[6] * inv + bb1.z, 0.f);
    float o7 = fmaxf(acc[7] * inv + bb1.w, 0.f);
    __half2 p0 = __floats2half2_rn(o0, o1);
    __half2 p1 = __floats2half2_rn(o2, o3);
    __half2 p2 = __floats2half2_rn(o4, o5);
    __half2 p3 = __floats2half2_rn(o6, o7);
    uint4 pk;
    pk.x = *(u32*)&p0; pk.y = *(u32*)&p1; pk.z = *(u32*)&p2; pk.w = *(u32*)&p3;
    *((uint4*)(g_out1h + (size_t)d * HC) + lane) = pk;
}

// ---------------- fused GAT layer 2 (1 head) + mean-pool red ------------------
__global__ void __launch_bounds__(256) gat2_k(const int* __restrict__ batch) {
    int w = (blockIdx.x * blockDim.x + threadIdx.x) >> 5;
    int lane = threadIdx.x & 31;
    if (w >= NN) return;
    const int d = w;

    float ald_d = g_ald2[d];
    float wself = __expf(leaky(g_als2[d] + ald_d));
    float ssum = wself;

    float acc[8];
    {
        uint4 q = *((const uint4*)(g_h2h + (size_t)d * HC) + lane);
        const __half2* h2 = (const __half2*)&q;
#pragma unroll
        for (int k = 0; k < 4; k++) {
            float2 f = __half22float2(h2[k]);
            acc[2 * k] = wself * f.x;
            acc[2 * k + 1] = wself * f.y;
        }
    }

    int beg = d * CAP;
    int end = beg + g_deg[d];

#define GAT2_STEP(SRC)                                                          \
    {                                                                           \
        int s_ = (SRC);                                                         \
        float we = __expf(leaky(g_als2[s_] + ald_d));                           \
        ssum += we;                                                             \
        uint4 q = *((const uint4*)(g_h2h + (size_t)s_ * HC) + lane);            \
        const __half2* h2 = (const __half2*)&q;                                 \
        _Pragma("unroll")                                                       \
        for (int k = 0; k < 4; k++) {                                           \
            float2 f = __half22float2(h2[k]);                                   \
            acc[2 * k]     = fmaf(we, f.x, acc[2 * k]);                         \
            acc[2 * k + 1] = fmaf(we, f.y, acc[2 * k + 1]);                     \
        }                                                                       \
    }

    for (int base = beg; base < end; base += 32) {
        int idx = base + lane;
        int sv = (idx < end) ? g_adj[idx] : 0;
        int n = min(32, end - base);
        if (n == 32) {
#pragma unroll 8
            for (int j = 0; j < 32; j++) GAT2_STEP(__shfl_sync(0xffffffffu, sv, j));
        } else {
            for (int j = 0; j < n; j++) GAT2_STEP(__shfl_sync(0xffffffffu, sv, j));
        }
    }

    float inv = 1.f / ssum;
    int g = batch[d];
    float4* sd = (float4*)(g_sums + g * HC) + 2 * lane;
    redAdd4(sd,     make_float4(acc[0] * inv, acc[1] * inv, acc[2] * inv, acc[3] * inv));
    redAdd4(sd + 1, make_float4(acc[4] * inv, acc[5] * inv, acc[6] * inv, acc[7] * inv));
    if (lane == 0) atomicAdd(&g_cnts[g], 1.f);
}

// ---------------- final: (mean + b2) @ lin_w + lin_b --------------------------
__global__ void final_k(const float* __restrict__ b2,
                        const float* __restrict__ lw,
                        const float* __restrict__ lb,
                        float* __restrict__ out) {
    __shared__ float p[HC];
    int g = blockIdx.x;
    float cnt = fmaxf(g_cnts[g], 1.f);
    p[threadIdx.x] = g_sums[g * HC + threadIdx.x] / cnt + b2[threadIdx.x];
    __syncthreads();
    if (threadIdx.x < LL) {
        float acc = lb[threadIdx.x];
#pragma unroll 8
        for (int d = 0; d < HC; d++)
            acc = fmaf(p[d], lw[d * LL + threadIdx.x], acc);
        out[g * LL + threadIdx.x] = acc;
    }
}

// ---------------- launch -------------------------------------------------------
extern "C" void kernel_launch(void* const* d_in, const int* in_sizes, int n_in,
                              void* d_out, int out_size) {
    const float* x      = (const float*)d_in[0];
    const int*   ei     = (const int*)d_in[1];
    const int*   batch  = (const int*)d_in[2];
    const float* W1     = (const float*)d_in[3];
    const float* a_src1 = (const float*)d_in[4];
    const float* a_dst1 = (const float*)d_in[5];
    const float* b1     = (const float*)d_in[6];
    const float* W2     = (const float*)d_in[7];
    const float* a_src2 = (const float*)d_in[8];
    const float* a_dst2 = (const float*)d_in[9];
    const float* b2     = (const float*)d_in[10];
    const float* lin_w  = (const float*)d_in[11];
    const float* lin_b  = (const float*)d_in[12];
    float* out = (float*)d_out;

    const int* src = ei;
    const int* dst = ei + EE;

    static cudaStream_t s_adj = nullptr, s_g2 = nullptr;
    static cudaEvent_t ev_fork = nullptr, ev_adj = nullptr, ev_w2 = nullptr;
    static cudaEvent_t ev_g1a = nullptr, ev_g2a = nullptr;
    if (!s_adj) {
        cudaStreamCreateWithFlags(&s_adj, cudaStreamNonBlocking);
        cudaStreamCreateWithFlags(&s_g2, cudaStreamNonBlocking);
        cudaEventCreateWithFlags(&ev_fork, cudaEventDisableTiming);
        cudaEventCreateWithFlags(&ev_adj, cudaEventDisableTiming);
        cudaEventCreateWithFlags(&ev_w2, cudaEventDisableTiming);
        cudaEventCreateWithFlags(&ev_g1a, cudaEventDisableTiming);
        cudaEventCreateWithFlags(&ev_g2a, cudaEventDisableTiming);
    }

    // side stream: init, adjacency, W2 convert
    cudaEventRecord(ev_fork, 0);
    cudaStreamWaitEvent(s_adj, ev_fork, 0);
    init_side_k<<<(GG * HC + 255) / 256, 256, 0, s_adj>>>();
    adj_fill<<<(EE / 4 + 255) / 256, 256, 0, s_adj>>>(src, dst);
    cudaEventRecord(ev_adj, s_adj);
    wconv2_k<<<(HC * HC + 255) / 256, 256, 0, s_adj>>>(W2);
    cudaEventRecord(ev_w2, s_adj);

    // main stream: W1 convert, layer-1 GEMM (+fused logits)
    wconv1_k<<<(FIN * HC + 255) / 256, 256>>>(W1);
    gemm_mma<1><<<(NN + 31) / 32, 256>>>(x, a_src1, a_dst1, 0);

    // join: gat1 needs adjacency; chunk A then B
    cudaStreamWaitEvent(0, ev_adj, 0);
    gat1_k<<<SPLIT / 8, 256>>>(b1, 0, SPLIT);
    cudaEventRecord(ev_g1a, 0);
    gat1_k<<<(NN - SPLIT + 7) / 8, 256>>>(b1, SPLIT, NN);

    // s_g2: gemm2 chunk A overlapped with gat1_B
    cudaStreamWaitEvent(s_g2, ev_g1a, 0);
    cudaStreamWaitEvent(s_g2, ev_w2, 0);
    gemm_mma<2><<<SPLIT / 32, 256, 0, s_g2>>>(nullptr, a_src2, a_dst2, 0);
    cudaEventRecord(ev_g2a, s_g2);

    // main: gemm2 chunk B after gat1_B (+w2t), then join chunk A, gat2, final
    cudaStreamWaitEvent(0, ev_w2, 0);
    gemm_mma<2><<<(NN - SPLIT + 31) / 32, 256>>>(nullptr, a_src2, a_dst2, SPLIT);
    cudaStreamWaitEvent(0, ev_g2a, 0);
    gat2_k<<<(NN * 32 + 255) / 256, 256>>>(batch);

    final_k<<<GG, 256>>>(b2, lin_w, lin_b, out);
}

// round 15
// speedup vs baseline: 1.0813x; 1.0813x over previous
#include <cuda_runtime.h>
#include <cuda_fp16.h>
#include <math.h>

#define NN 10000
#define EE 320000
#define FIN 128
#define HC 256
#define NH1 16
#define GG 64
#define LL 10
#define CAP 256

typedef unsigned int u32;

// ---------------- scratch ----------------------------------------------------
__device__ __half g_h1h[NN * HC];
__device__ __half g_h2h[NN * HC];
__device__ __half g_out1h[NN * HC];  // relu(gat1_out + b1) in fp16
__device__ __half g_w1t[HC * FIN];   // W1^T fp16 [n][k]
__device__ __half g_w2t[HC * HC];    // W2^T fp16 [n][k]
__device__ float g_als1[NN * NH1];
__device__ float g_ald1[NN * NH1];
__device__ float g_als2[NN];
__device__ float g_ald2[NN];
__device__ float g_sums[GG * HC];
__device__ float g_cnts[GG];
__device__ int   g_deg[NN];
__device__ int   g_adj[NN * CAP];

__device__ __forceinline__ float leaky(float v) { return v >= 0.f ? v : 0.2f * v; }

__device__ __forceinline__ void redAdd4(float4* addr, float4 v) {
    asm volatile("red.global.add.v4.f32 [%0], {%1, %2, %3, %4};"
                 :: "l"(addr), "f"(v.x), "f"(v.y), "f"(v.z), "f"(v.w) : "memory");
}

__device__ __forceinline__ void mma16816(float* c, u32 a0, u32 a1, u32 a2, u32 a3,
                                         u32 b0, u32 b1) {
    asm volatile(
        "mma.sync.aligned.m16n8k16.row.col.f32.f16.f16.f32 "
        "{%0,%1,%2,%3}, {%4,%5,%6,%7}, {%8,%9}, {%0,%1,%2,%3};"
        : "+f"(c[0]), "+f"(c[1]), "+f"(c[2]), "+f"(c[3])
        : "r"(a0), "r"(a1), "r"(a2), "r"(a3), "r"(b0), "r"(b1));
}

__device__ __forceinline__ void ldsm4(u32& r0, u32& r1, u32& r2, u32& r3, u32 saddr) {
    asm volatile("ldmatrix.sync.aligned.m8n8.x4.shared.b16 {%0,%1,%2,%3}, [%4];"
                 : "=r"(r0), "=r"(r1), "=r"(r2), "=r"(r3) : "r"(saddr));
}

__device__ __forceinline__ u32 smem_u32(const void* p) {
    return (u32)__cvta_generic_to_shared(p);
}

__device__ __forceinline__ float red4(float v) {   // sum over 4-lane group
    v += __shfl_down_sync(0xffffffffu, v, 1);
    v += __shfl_down_sync(0xffffffffu, v, 2);
    return v;
}

// ---------------- side-stream init + adjacency --------------------------------
__global__ void init_side_k() {
    int i = blockIdx.x * blockDim.x + threadIdx.x;
    if (i < NN) g_deg[i] = 0;
    if (i < GG * HC) g_sums[i] = 0.f;
    if (i < GG) g_cnts[i] = 0.f;
}

__global__ void adj_fill(const int* __restrict__ src, const int* __restrict__ dst) {
    int i = blockIdx.x * blockDim.x + threadIdx.x;
    if (i * 4 >= EE) return;
    int4 s4 = ((const int4*)src)[i];
    int4 d4 = ((const int4*)dst)[i];
    int p;
    p = atomicAdd(&g_deg[d4.x], 1); g_adj[d4.x * CAP + p] = s4.x;
    p = atomicAdd(&g_deg[d4.y], 1); g_adj[d4.y * CAP + p] = s4.y;
    p = atomicAdd(&g_deg[d4.z], 1); g_adj[d4.z * CAP + p] = s4.z;
    p = atomicAdd(&g_deg[d4.w], 1); g_adj[d4.w * CAP + p] = s4.w;
}

// tiled transpose+convert: W [K][256] fp32 -> Wt [256][K] fp16
// NOTE: output selected by template (device-side) — device globals must NOT be
// passed as host-side kernel args (host shadow address bug; broke R12/R13).
template <int LAYER>
__global__ void __launch_bounds__(256) wconv_k(const float* __restrict__ W) {
    constexpr int K = (LAYER == 1) ? FIN : HC;
    __half* __restrict__ Wt = (LAYER == 1) ? g_w1t : g_w2t;
    __shared__ __half t[32][33];
    int bk = blockIdx.x & (K / 32 - 1);
    int bn = blockIdx.x / (K / 32);
    int k0 = bk * 32, n0 = bn * 32;
    int lx = threadIdx.x & 31, ly = threadIdx.x >> 5;
#pragma unroll
    for (int i = 0; i < 4; i++) {
        int k = k0 + ly + 8 * i;
        t[lx][ly + 8 * i] = __float2half_rn(W[k * HC + n0 + lx]);
    }
    __syncthreads();
#pragma unroll
    for (int i = 0; i < 4; i++) {
        int n = n0 + ly + 8 * i;
        Wt[n * K + k0 + lx] = t[ly + 8 * i][lx];
    }
}

// ---------------- tensor-core GEMM + fused logits (ldmatrix) -------------------
// block: 32 rows x 256 cols, 8 warps as 2 row-groups x 4 col-groups.
#define KC 64
#define LDA 72
#define LDB 72

template <int LAYER>
__global__ void __launch_bounds__(256) gemm_mma(const float* __restrict__ Xin,
                                                const float* __restrict__ a_src,
                                                const float* __restrict__ a_dst) {
    constexpr int K = (LAYER == 1) ? FIN : HC;
    const __half* __restrict__ Wt = (LAYER == 1) ? g_w1t : g_w2t;
    __half* __restrict__ Hout = (LAYER == 1) ? g_h1h : g_h2h;

    __shared__ __half As[32 * LDA];
    __shared__ __half Ws[256 * LDB];
    __shared__ float red_s[32][5];
    __shared__ float red_d[32][5];

    int row0 = blockIdx.x * 32;
    int tid = threadIdx.x;
    int warp = tid >> 5, lane = tid & 31;
    int gr = lane >> 2, tg = lane & 3;
    int rig = lane & 7, grp = lane >> 3;     // ldmatrix addressing
    int wr = (warp & 1) * 16;
    int wc = (warp >> 1) * 64;

    float c[8][4];
#pragma unroll
    for (int t = 0; t < 8; t++)
#pragma unroll
        for (int j = 0; j < 4; j++) c[t][j] = 0.f;

    for (int kc0 = 0; kc0 < K; kc0 += KC) {
        // --- A chunk: 32 rows x 64 k ---
        {
            int r = tid >> 3, cc = (tid & 7) * 8;
            int row = row0 + r;
            uint4 pk = {0, 0, 0, 0};
            if (row < NN) {
                if (LAYER == 1) {
                    const float4* p = (const float4*)(Xin + (size_t)row * K + kc0 + cc);
                    float4 v0 = p[0], v1 = p[1];
                    __half2 h0 = __floats2half2_rn(v0.x, v0.y);
                    __half2 h1 = __floats2half2_rn(v0.z, v0.w);
                    __half2 h2 = __floats2half2_rn(v1.x, v1.y);
                    __half2 h3 = __floats2half2_rn(v1.z, v1.w);
                    pk.x = *(u32*)&h0; pk.y = *(u32*)&h1;
                    pk.z = *(u32*)&h2; pk.w = *(u32*)&h3;
                } else {
                    pk = *(const uint4*)(g_out1h + (size_t)row * K + kc0 + cc);
                }
            }
            *(uint4*)(As + r * LDA + cc) = pk;
        }
        // --- W chunk: 256 n-rows x 64 k ---
        {
            int cc = (tid & 7) * 8;
#pragma unroll
            for (int pass = 0; pass < 8; pass++) {
                int n = pass * 32 + (tid >> 3);
                uint4 v = *(const uint4*)(Wt + (size_t)n * K + kc0 + cc);
                *(uint4*)(Ws + n * LDB + cc) = v;
            }
        }
        __syncthreads();

#pragma unroll
        for (int ks = 0; ks < KC; ks += 16) {
            u32 a0, a1, a2, a3;
            {
                // matrices: (m0-7,k0),(m8-15,k0),(m0-7,k8),(m8-15,k8)
                u32 ad = smem_u32(As + (wr + (grp & 1) * 8 + rig) * LDA
                                     + ks + (grp >> 1) * 8);
                ldsm4(a0, a1, a2, a3, ad);
            }
#pragma unroll
            for (int tp = 0; tp < 8; tp += 2) {
                // matrices: (t,k0),(t,k8),(t+1,k0),(t+1,k8)
                int tt = (grp < 2) ? tp : tp + 1;
                u32 bd = smem_u32(Ws + (wc + tt * 8 + rig) * LDB
                                     + ks + (grp & 1) * 8);
                u32 b0, b1, b2, b3;
                ldsm4(b0, b1, b2, b3, bd);
                mma16816(c[tp],     a0, a1, a2, a3, b0, b1);
                mma16816(c[tp + 1], a0, a1, a2, a3, b2, b3);
            }
        }
        __syncthreads();
    }

    int r_a = row0 + wr + gr;
    int r_b = r_a + 8;

    float vsa[8], vda[8], vsb[8], vdb[8];
#pragma unroll
    for (int t = 0; t < 8; t++) {
        int col = wc + t * 8 + tg * 2;
        if (r_a < NN) {
            __half2 ha = __floats2half2_rn(c[t][0], c[t][1]);
            *(u32*)&Hout[(size_t)r_a * HC + col] = *(u32*)&ha;
        }
        if (r_b < NN) {
            __half2 hb = __floats2half2_rn(c[t][2], c[t][3]);
            *(u32*)&Hout[(size_t)r_b * HC + col] = *(u32*)&hb;
        }
        float as0 = a_src[col], as1 = a_src[col + 1];
        float ad0 = a_dst[col], ad1 = a_dst[col + 1];
        vsa[t] = c[t][0] * as0 + c[t][1] * as1;
        vda[t] = c[t][0] * ad0 + c[t][1] * ad1;
        vsb[t] = c[t][2] * as0 + c[t][3] * as1;
        vdb[t] = c[t][2] * ad0 + c[t][3] * ad1;
    }

    if (LAYER == 1) {
        int hb = (warp >> 1) * 4;
#pragma unroll
        for (int h = 0; h < 4; h++) {
            float sa = red4(vsa[2 * h] + vsa[2 * h + 1]);
            float da = red4(vda[2 * h] + vda[2 * h + 1]);
            float sb = red4(vsb[2 * h] + vsb[2 * h + 1]);
            float db = red4(vdb[2 * h] + vdb[2 * h + 1]);
            if (tg == 0) {
                if (r_a < NN) { g_als1[r_a * NH1 + hb + h] = sa; g_ald1[r_a * NH1 + hb + h] = da; }
                if (r_b < NN) { g_als1[r_b * NH1 + hb + h] = sb; g_ald1[r_b * NH1 + hb + h] = db; }
            }
        }
    } else {
        float sa = red4(vsa[0] + vsa[1] + vsa[2] + vsa[3] + vsa[4] + vsa[5] + vsa[6] + vsa[7]);
        float da = red4(vda[0] + vda[1] + vda[2] + vda[3] + vda[4] + vda[5] + vda[6] + vda[7]);
        float sb = red4(vsb[0] + vsb[1] + vsb[2] + vsb[3] + vsb[4] + vsb[5] + vsb[6] + vsb[7]);
        float db = red4(vdb[0] + vdb[1] + vdb[2] + vdb[3] + vdb[4] + vdb[5] + vdb[6] + vdb[7]);
        if (tg == 0) {
            int cg = warp >> 1;
            red_s[wr + gr][cg] = sa; red_s[wr + gr + 8][cg] = sb;
            red_d[wr + gr][cg] = da; red_d[wr + gr + 8][cg] = db;
        }
        __syncthreads();
        if (tid < 64) {
            int row = tid >> 1, sel = tid & 1;
            if (row0 + row < NN) {
                const float (*rp)[5] = sel ? red_d : red_s;
                float s = rp[row][0] + rp[row][1] + rp[row][2] + rp[row][3];
                if (sel) g_ald2[row0 + row] = s;
                else     g_als2[row0 + row] = s;
            }
        }
    }
}

// ---------------- fused GAT layer 1: fp16 gather, epilogue b1+relu fp16 -------
__global__ void __launch_bounds__(256) gat1_k(const float* __restrict__ b1) {
    int w = (blockIdx.x * blockDim.x + threadIdx.x) >> 5;
    int lane = threadIdx.x & 31;
    if (w >= NN) return;
    const int d = w;
    const int hh = lane >> 1;

    float ald_h = g_ald1[d * NH1 + hh];
    float wself = __expf(leaky(g_als1[d * NH1 + hh] + ald_h));
    float ssum = wself;

    float acc[8];
    {
        uint4 q = *((const uint4*)(g_h1h + (size_t)d * HC) + lane);
        const __half2* h2 = (const __half2*)&q;
#pragma unroll
        for (int k = 0; k < 4; k++) {
            float2 f = __half22float2(h2[k]);
            acc[2 * k] = wself * f.x;
            acc[2 * k + 1] = wself * f.y;
        }
    }

    int beg = d * CAP;
    int end = beg + g_deg[d];

#define GAT1_STEP(SRC)                                                          \
    {                                                                           \
        int s_ = (SRC);                                                         \
        float we = __expf(leaky(g_als1[s_ * NH1 + hh] + ald_h));                \
        ssum += we;                                                             \
        uint4 q = *((const uint4*)(g_h1h + (size_t)s_ * HC) + lane);            \
        const __half2* h2 = (const __half2*)&q;                                 \
        _Pragma("unroll")                                                       \
        for (int k = 0; k < 4; k++) {                                           \
            float2 f = __half22float2(h2[k]);                                   \
            acc[2 * k]     = fmaf(we, f.x, acc[2 * k]);                         \
            acc[2 * k + 1] = fmaf(we, f.y, acc[2 * k + 1]);                     \
        }                                                                       \
    }

    for (int base = beg; base < end; base += 32) {
        int idx = base + lane;
        int sv = (idx < end) ? g_adj[idx] : 0;
        int n = min(32, end - base);
        if (n == 32) {
#pragma unroll 8
            for (int j = 0; j < 32; j++) GAT1_STEP(__shfl_sync(0xffffffffu, sv, j));
        } else {
            for (int j = 0; j < n; j++) GAT1_STEP(__shfl_sync(0xffffffffu, sv, j));
        }
    }

    float inv = 1.f / ssum;
    const float4* b4 = (const float4*)(b1 + lane * 8);
    float4 bb0 = b4[0], bb1 = b4[1];
    float o0 = fmaxf(acc[0] * inv + bb0.x, 0.f);
    float o1 = fmaxf(acc[1] * inv + bb0.y, 0.f);
    float o2 = fmaxf(acc[2] * inv + bb0.z, 0.f);
    float o3 = fmaxf(acc[3] * inv + bb0.w, 0.f);
    float o4 = fmaxf(acc[4] * inv + bb1.x, 0.f);
    float o5 = fmaxf(acc[5] * inv + bb1.y, 0.f);
    float o6 = fmaxf(acc[6] * inv + bb1.z, 0.f);
    float o7 = fmaxf(acc[7] * inv + bb1.w, 0.f);
    __half2 p0 = __floats2half2_rn(o0, o1);
    __half2 p1 = __floats2half2_rn(o2, o3);
    __half2 p2 = __floats2half2_rn(o4, o5);
    __half2 p3 = __floats2half2_rn(o6, o7);
    uint4 pk;
    pk.x = *(u32*)&p0; pk.y = *(u32*)&p1; pk.z = *(u32*)&p2; pk.w = *(u32*)&p3;
    *((uint4*)(g_out1h + (size_t)d * HC) + lane) = pk;
}

// ---------------- fused GAT layer 2 (1 head) + mean-pool red ------------------
__global__ void __launch_bounds__(256) gat2_k(const int* __restrict__ batch) {
    int w = (blockIdx.x * blockDim.x + threadIdx.x) >> 5;
    int lane = threadIdx.x & 31;
    if (w >= NN) return;
    const int d = w;

    float ald_d = g_ald2[d];
    float wself = __expf(leaky(g_als2[d] + ald_d));
    float ssum = wself;

    float acc[8];
    {
        uint4 q = *((const uint4*)(g_h2h + (size_t)d * HC) + lane);
        const __half2* h2 = (const __half2*)&q;
#pragma unroll
        for (int k = 0; k < 4; k++) {
            float2 f = __half22float2(h2[k]);
            acc[2 * k] = wself * f.x;
            acc[2 * k + 1] = wself * f.y;
        }
    }

    int beg = d * CAP;
    int end = beg + g_deg[d];

#define GAT2_STEP(SRC)                                                          \
    {                                                                           \
        int s_ = (SRC);                                                         \
        float we = __expf(leaky(g_als2[s_] + ald_d));                           \
        ssum += we;                                                             \
        uint4 q = *((const uint4*)(g_h2h + (size_t)s_ * HC) + lane);            \
        const __half2* h2 = (const __half2*)&q;                                 \
        _Pragma("unroll")                                                       \
        for (int k = 0; k < 4; k++) {                                           \
            float2 f = __half22float2(h2[k]);                                   \
            acc[2 * k]     = fmaf(we, f.x, acc[2 * k]);                         \
            acc[2 * k + 1] = fmaf(we, f.y, acc[2 * k + 1]);                     \
        }                                                                       \
    }

    for (int base = beg; base < end; base += 32) {
        int idx = base + lane;
        int sv = (idx < end) ? g_adj[idx] : 0;
        int n = min(32, end - base);
        if (n == 32) {
#pragma unroll 8
            for (int j = 0; j < 32; j++) GAT2_STEP(__shfl_sync(0xffffffffu, sv, j));
        } else {
            for (int j = 0; j < n; j++) GAT2_STEP(__shfl_sync(0xffffffffu, sv, j));
        }
    }

    float inv = 1.f / ssum;
    int g = batch[d];
    float4* sd = (float4*)(g_sums + g * HC) + 2 * lane;
    redAdd4(sd,     make_float4(acc[0] * inv, acc[1] * inv, acc[2] * inv, acc[3] * inv));
    redAdd4(sd + 1, make_float4(acc[4] * inv, acc[5] * inv, acc[6] * inv, acc[7] * inv));
    if (lane == 0) atomicAdd(&g_cnts[g], 1.f);
}

// ---------------- final: (mean + b2) @ lin_w + lin_b --------------------------
__global__ void final_k(const float* __restrict__ b2,
                        const float* __restrict__ lw,
                        const float* __restrict__ lb,
                        float* __restrict__ out) {
    __shared__ float p[HC];
    int g = blockIdx.x;
    float cnt = fmaxf(g_cnts[g], 1.f);
    p[threadIdx.x] = g_sums[g * HC + threadIdx.x] / cnt + b2[threadIdx.x];
    __syncthreads();
    if (threadIdx.x < LL) {
        float acc = lb[threadIdx.x];
#pragma unroll 8
        for (int d = 0; d < HC; d++)
            acc = fmaf(p[d], lw[d * LL + threadIdx.x], acc);
        out[g * LL + threadIdx.x] = acc;
    }
}

// ---------------- launch -------------------------------------------------------
extern "C" void kernel_launch(void* const* d_in, const int* in_sizes, int n_in,
                              void* d_out, int out_size) {
    const float* x      = (const float*)d_in[0];
    const int*   ei     = (const int*)d_in[1];
    const int*   batch  = (const int*)d_in[2];
    const float* W1     = (const float*)d_in[3];
    const float* a_src1 = (const float*)d_in[4];
    const float* a_dst1 = (const float*)d_in[5];
    const float* b1     = (const float*)d_in[6];
    const float* W2     = (const float*)d_in[7];
    const float* a_src2 = (const float*)d_in[8];
    const float* a_dst2 = (const float*)d_in[9];
    const float* b2     = (const float*)d_in[10];
    const float* lin_w  = (const float*)d_in[11];
    const float* lin_b  = (const float*)d_in[12];
    float* out = (float*)d_out;

    const int* src = ei;
    const int* dst = ei + EE;

    static cudaStream_t s_adj = nullptr;
    static cudaEvent_t ev_fork = nullptr, ev_adj = nullptr, ev_w2 = nullptr;
    if (!s_adj) {
        cudaStreamCreateWithFlags(&s_adj, cudaStreamNonBlocking);
        cudaEventCreateWithFlags(&ev_fork, cudaEventDisableTiming);
        cudaEventCreateWithFlags(&ev_adj, cudaEventDisableTiming);
        cudaEventCreateWithFlags(&ev_w2, cudaEventDisableTiming);
    }

    // side stream: init, adjacency, W2 convert
    cudaEventRecord(ev_fork, 0);
    cudaStreamWaitEvent(s_adj, ev_fork, 0);
    init_side_k<<<(GG * HC + 255) / 256, 256, 0, s_adj>>>();
    adj_fill<<<(EE / 4 + 255) / 256, 256, 0, s_adj>>>(src, dst);
    cudaEventRecord(ev_adj, s_adj);
    wconv_k<2><<<(HC / 32) * (HC / 32), 256, 0, s_adj>>>(W2);
    cudaEventRecord(ev_w2, s_adj);

    // main stream: W1 convert (tiled), layer-1 GEMM (+fused logits)
    wconv_k<1><<<(FIN / 32) * (HC / 32), 256>>>(W1);
    gemm_mma<1><<<(NN + 31) / 32, 256>>>(x, a_src1, a_dst1);

    // join: gat1 needs adjacency
    cudaStreamWaitEvent(0, ev_adj, 0);
    gat1_k<<<(NN * 32 + 255) / 256, 256>>>(b1);

    // join: gemm2 needs w2t
    cudaStreamWaitEvent(0, ev_w2, 0);
    gemm_mma<2><<<(NN + 31) / 32, 256>>>(nullptr, a_src2, a_dst2);
    gat2_k<<<(NN * 32 + 255) / 256, 256>>>(batch);

    final_k<<<GG, 256>>>(b2, lin_w, lin_b, out);
}